// round 2
// baseline (speedup 1.0000x reference)
#include <cuda_runtime.h>
#include <math.h>

#define Hdim 1024
#define Vdim 100000
#define Tn   64
#define KTOP 20
#define NTH  1024
#define MAXB 152

// Output layout (flattened reference pytree, float32):
//   a_hats[64], feedbacks[64], masked_probs[64*100000], hidden[64*1024], cell[64*1024]
#define OFF_AHAT 0
#define OFF_FB   Tn
#define OFF_P    (2*Tn)
#define OFF_H    ((size_t)(2*Tn) + (size_t)Tn*(size_t)Vdim)
#define OFF_C    (OFF_H + (size_t)Tn*(size_t)Hdim)

// -------- persistent scratch (device globals; no allocation) --------
__device__ float g_h[2][Hdim];
__device__ float g_c[Hdim];
__device__ float g_mask[Vdim];
__device__ float g_e[Vdim];
__device__ unsigned long long g_cand[MAXB*KTOP];
__device__ float g_Z[2];
__device__ int   g_ahat;
__device__ float g_fb;
__device__ int   g_flag;
__device__ unsigned g_barc;
__device__ unsigned g_bars;

__device__ __forceinline__ unsigned ordf(float f){
    unsigned u = __float_as_uint(f);
    return (u & 0x80000000u) ? ~u : (u | 0x80000000u);
}
__device__ __forceinline__ float sigm(float xv){ return 1.0f/(1.0f+expf(-xv)); }

__device__ __forceinline__ unsigned long long wmax64(unsigned long long v){
    #pragma unroll
    for (int off = 16; off; off >>= 1){
        unsigned long long o = __shfl_xor_sync(0xffffffffu, v, off);
        if (o > v) v = o;
    }
    return v;
}

// descending-by-lane bitonic sort of one 64-bit key per lane (shuffle-only)
__device__ __forceinline__ unsigned long long bitonic_desc(unsigned long long key, int lane){
    unsigned long long x = ~key;            // sort ascending of ~key == descending of key
    #pragma unroll
    for (int k = 2; k <= 32; k <<= 1){
        #pragma unroll
        for (int j = k >> 1; j > 0; j >>= 1){
            unsigned long long o = __shfl_xor_sync(0xffffffffu, x, j);
            bool up      = ((lane & k) == 0);
            bool low     = ((lane & j) == 0);
            bool takeMin = (low == up);
            bool oless   = (o < x);
            x = takeMin ? (oless ? o : x) : (oless ? x : o);
        }
    }
    return ~x;
}

__device__ __forceinline__ void gridbar(volatile unsigned* s_sense){
    __syncthreads();
    if (threadIdx.x == 0){
        unsigned target = (*s_sense) ^ 1u;
        *s_sense = target;
        __threadfence();
        unsigned arrived = atomicAdd(&g_barc, 1u) + 1u;
        if (arrived == gridDim.x){
            atomicExch(&g_barc, 0u);
            __threadfence();
            atomicExch(&g_bars, target);
        } else {
            while (atomicAdd(&g_bars, 0u) != target){ __nanosleep(128); }
        }
        __threadfence();
    }
    __syncthreads();
}

__global__ void init_kernel(){
    int i = blockIdx.x*blockDim.x + threadIdx.x;
    if (i < Vdim) g_mask[i] = 1.0f;
    if (i < Hdim){ g_h[0][i]=0.f; g_h[1][i]=0.f; g_c[i]=0.f; }
    if (i == 0){
        g_Z[0]=0.f; g_Z[1]=0.f; g_ahat=0; g_fb=0.f;
        g_flag=-1; g_barc=0u; g_bars=0u;
    }
}

__global__ __launch_bounds__(NTH, 1)
void lstm_rec_kernel(const int* __restrict__ x, int nx,
                     const float* __restrict__ embed,
                     const float* __restrict__ W_ih,
                     const float* __restrict__ W_hh,
                     const float* __restrict__ b_ih,
                     const float* __restrict__ b_hh,
                     const float* __restrict__ W_out,
                     const float* __restrict__ b_out,
                     float* __restrict__ out)
{
    const int tid  = threadIdx.x;
    const int bid  = blockIdx.x;
    const int nb   = gridDim.x;
    const int lane = tid & 31;
    const int wid  = tid >> 5;

    __shared__ float s_h[Hdim];
    __shared__ unsigned long long s_key[NTH];        // per-warp sorted keys
    __shared__ unsigned long long s_m[32*KTOP];      // block0 merge lists
    __shared__ float s_z[32];
    __shared__ int s_items[KTOP];
    __shared__ int s_hit[KTOP];
    __shared__ int s_ah;
    __shared__ float s_fb;
    __shared__ unsigned s_sense;

    if (tid == 0){ s_sense = 0u; s_ah = 0; s_fb = 0.f; }
    __syncthreads();

    const int chunk = (Vdim + nb - 1) / nb;
    const int v0 = bid * chunk;
    int cnt = Vdim - v0; if (cnt > chunk) cnt = chunk; if (cnt < 0) cnt = 0;

    for (int t = 0; t < Tn; ++t){
        // ============ Phase A: mask update, Z reset, LSTM cell ============
        if (tid == 0){
            if (t > 0 && s_ah >= v0 && s_ah < v0 + cnt) g_mask[s_ah] = 0.f; // owner-block
            if (bid == nb - 1) g_Z[t & 1] = 0.f;   // last readers were step t-2 (2 barriers ago)
        }
        if (bid < 32){
            const int j = (bid << 5) + wid;                       // hidden unit 0..1023
            const float fb = s_fb;
            const int   ah = s_ah;
            const float4* __restrict__ e4p = ((const float4*)embed) + (size_t)ah * (Hdim/4);
            const float4* __restrict__ hp4 = (const float4*)(g_h[(t & 1) ^ 1]);
            const float4* __restrict__ wi4 = (const float4*)W_ih;
            const float4* __restrict__ wh4 = (const float4*)W_hh;
            const size_t r0 = (size_t)(0*Hdim + j) * (Hdim/4);
            const size_t r1 = (size_t)(1*Hdim + j) * (Hdim/4);
            const size_t r2 = (size_t)(2*Hdim + j) * (Hdim/4);
            const size_t r3 = (size_t)(3*Hdim + j) * (Hdim/4);
            float a0=0.f,a1=0.f,a2=0.f,a3=0.f;
            #pragma unroll
            for (int q = 0; q < 8; ++q){
                const int idx = lane + (q << 5);
                float4 ev = e4p[idx];
                float4 hv = __ldcg(hp4 + idx);                    // cross-block data
                float4 xv = make_float4(ev.x*fb, ev.y*fb, ev.z*fb, ev.w*fb);
                float4 w;
                w = wi4[r0+idx]; a0 += w.x*xv.x+w.y*xv.y+w.z*xv.z+w.w*xv.w;
                w = wh4[r0+idx]; a0 += w.x*hv.x+w.y*hv.y+w.z*hv.z+w.w*hv.w;
                w = wi4[r1+idx]; a1 += w.x*xv.x+w.y*xv.y+w.z*xv.z+w.w*xv.w;
                w = wh4[r1+idx]; a1 += w.x*hv.x+w.y*hv.y+w.z*hv.z+w.w*hv.w;
                w = wi4[r2+idx]; a2 += w.x*xv.x+w.y*xv.y+w.z*xv.z+w.w*xv.w;
                w = wh4[r2+idx]; a2 += w.x*hv.x+w.y*hv.y+w.z*hv.z+w.w*hv.w;
                w = wi4[r3+idx]; a3 += w.x*xv.x+w.y*xv.y+w.z*xv.z+w.w*xv.w;
                w = wh4[r3+idx]; a3 += w.x*hv.x+w.y*hv.y+w.z*hv.z+w.w*hv.w;
            }
            #pragma unroll
            for (int off=16; off; off>>=1){
                a0 += __shfl_down_sync(0xffffffffu, a0, off);
                a1 += __shfl_down_sync(0xffffffffu, a1, off);
                a2 += __shfl_down_sync(0xffffffffu, a2, off);
                a3 += __shfl_down_sync(0xffffffffu, a3, off);
            }
            if (lane == 0){
                float gi = a0 + b_ih[j]        + b_hh[j];
                float gf = a1 + b_ih[Hdim+j]   + b_hh[Hdim+j];
                float gg = a2 + b_ih[2*Hdim+j] + b_hh[2*Hdim+j];
                float go = a3 + b_ih[3*Hdim+j] + b_hh[3*Hdim+j];
                float iv = sigm(gi), fv = sigm(gf), gv = tanhf(gg), ov = sigm(go);
                float cv = fv * g_c[j] + iv * gv;
                g_c[j] = cv;
                float hv = ov * tanhf(cv);
                g_h[t & 1][j] = hv;
                out[OFF_H + (size_t)t*Hdim + j] = hv;
                out[OFF_C + (size_t)t*Hdim + j] = cv;
            }
        }
        gridbar(&s_sense);

        // ============ Phase B: logits, exp-sum, per-block top-20 ============
        s_h[tid] = __ldcg(&g_h[t & 1][tid]);                      // Hdim == NTH
        __syncthreads();
        const float4* s_h4 = (const float4*)s_h;

        float zacc = 0.f;
        for (int r = wid; r < cnt; r += 32){
            const int v = v0 + r;
            const float4* __restrict__ wr = ((const float4*)W_out) + (size_t)v * (Hdim/4);
            float acc = 0.f;
            #pragma unroll
            for (int q = 0; q < 8; ++q){
                const int idx = lane + (q << 5);
                float4 w  = __ldcs(wr + idx);                     // streaming: keep LSTM wts in L2
                float4 hh = s_h4[idx];
                acc += w.x*hh.x + w.y*hh.y + w.z*hh.z + w.w*hh.w;
            }
            #pragma unroll
            for (int off=16; off; off>>=1) acc += __shfl_down_sync(0xffffffffu, acc, off);
            if (lane == 0){
                float l = acc + b_out[v];
                float e = expf(l);
                g_e[v] = e;
                zacc += e;
                float m = g_mask[v];                              // owner-block coherent
                s_key[r] = (m != 0.f)
                    ? ((((unsigned long long)ordf(l)) << 32) | (unsigned long long)(~(unsigned)v))
                    : 0ULL;
            }
        }
        if (lane == 0) s_z[wid] = zacc;
        __syncthreads();
        if (wid == 0){
            float z = (lane < 32) ? s_z[lane] : 0.f;
            #pragma unroll
            for (int off=16; off; off>>=1) z += __shfl_down_sync(0xffffffffu, z, off);
            if (lane == 0) atomicAdd(&g_Z[t & 1], z);
        }
        // per-warp bitonic sort (no syncs), then warp0 merges 32 sorted lists
        {
            unsigned long long kr = (tid < cnt) ? s_key[tid] : 0ULL;
            __syncthreads();                                      // s_key reads done
            kr = bitonic_desc(kr, lane);
            s_key[tid] = kr;                                      // lane i = i-th largest of warp
            __syncthreads();
            if (wid == 0){
                int ptr = 0;
                unsigned long long head = s_key[lane * 32];
                #pragma unroll
                for (int it = 0; it < KTOP; ++it){
                    unsigned long long m = wmax64(head);
                    unsigned ball = __ballot_sync(0xffffffffu, head == m);
                    int wl = __ffs(ball) - 1;
                    if (lane == wl){
                        ++ptr;
                        head = (ptr < 32) ? s_key[lane * 32 + ptr] : 0ULL;
                    }
                    if (lane == 0) g_cand[bid*KTOP + it] = m;
                }
            }
        }
        gridbar(&s_sense);

        // ============ Phase C: control (block0) overlapped with prob writes ============
        if (bid == 0){
            const int ncand = nb * KTOP;
            const int per = (ncand + 31) / 32;                    // <= 95
            const int base = wid * per;
            int mycnt = ncand - base;
            if (mycnt > per) mycnt = per; if (mycnt < 0) mycnt = 0;
            unsigned long long c0 = (lane      < mycnt) ? __ldcg(&g_cand[base + lane     ]) : 0ULL;
            unsigned long long c1 = (lane + 32 < mycnt) ? __ldcg(&g_cand[base + lane + 32]) : 0ULL;
            unsigned long long c2 = (lane + 64 < mycnt) ? __ldcg(&g_cand[base + lane + 64]) : 0ULL;
            #pragma unroll
            for (int it = 0; it < KTOP; ++it){                    // per-warp top-20 (shuffle-only)
                unsigned long long loc = c0;
                if (c1 > loc) loc = c1;
                if (c2 > loc) loc = c2;
                unsigned long long m = wmax64(loc);
                if      (c0 == m) c0 = 0ULL;
                else if (c1 == m) c1 = 0ULL;
                else if (c2 == m) c2 = 0ULL;
                if (lane == 0) s_m[wid*KTOP + it] = m;
            }
            __syncthreads();
            if (wid == 0){                                        // 32-way merge of sorted lists
                int ptr = 0;
                unsigned long long head = s_m[lane * KTOP];
                #pragma unroll
                for (int it = 0; it < KTOP; ++it){
                    unsigned long long m = wmax64(head);
                    unsigned ball = __ballot_sync(0xffffffffu, head == m);
                    int wl = __ffs(ball) - 1;
                    if (lane == wl){
                        ++ptr;
                        head = (ptr < KTOP) ? s_m[lane * KTOP + ptr] : 0ULL;
                    }
                    if (lane == 0) s_items[it] = (int)(~(unsigned)(m & 0xffffffffu));
                }
            }
            __syncthreads();
            if (tid < KTOP){
                const int want = s_items[tid] + 1;                // 1-indexed compare
                int h = 0;
                for (int jx = 0; jx < nx; ++jx) h |= (x[jx] == want);
                s_hit[tid] = h;
            }
            __syncthreads();
            if (tid == 0){
                int card = 0, first = -1;
                #pragma unroll
                for (int k2 = 0; k2 < KTOP; ++k2){
                    if (s_hit[k2]){ ++card; if (first < 0) first = k2; }
                }
                const int ah = (card > 0) ? s_items[first] : s_items[0];
                const float fbn = (card > 0) ? 1.f : -1.f;
                s_ah = ah; s_fb = fbn;
                g_ahat = ah; g_fb = fbn;
                out[OFF_AHAT + t] = (float)ah;
                out[OFF_FB + t]   = fbn;
                __threadfence();
                atomicExch(&g_flag, t);                           // publish step-t control
            }
        }
        // all blocks: masked-prob writes (overlaps block0's control)
        {
            const float Zinv = 1.0f / __ldcg(&g_Z[t & 1]);
            for (int r = tid; r < cnt; r += NTH){
                const int v = v0 + r;
                __stcs(&out[OFF_P + (size_t)t*Vdim + v], g_e[v] * Zinv * g_mask[v]);
            }
        }
        if (bid != 0 && tid == 0){
            while (atomicAdd(&g_flag, 0) < t){ __nanosleep(64); }
            __threadfence();
            s_ah = __ldcg(&g_ahat);
            s_fb = __ldcg(&g_fb);
        }
        __syncthreads();                                          // s_ah/s_fb block-visible
    }
}

extern "C" void kernel_launch(void* const* d_in, const int* in_sizes, int n_in,
                              void* d_out, int out_size)
{
    const int*   x     = (const int*)  d_in[0];
    const float* embed = (const float*)d_in[1];
    const float* W_ih  = (const float*)d_in[2];
    const float* W_hh  = (const float*)d_in[3];
    const float* b_ih  = (const float*)d_in[4];
    const float* b_hh  = (const float*)d_in[5];
    const float* W_out = (const float*)d_in[6];
    const float* b_out = (const float*)d_in[7];
    float* out = (float*)d_out;
    const int nx = in_sizes[0];

    int dev = 0;
    cudaGetDevice(&dev);
    int sm = 148;
    cudaDeviceGetAttribute(&sm, cudaDevAttrMultiProcessorCount, dev);
    int grid = sm < MAXB ? sm : MAXB;   // 1024 thr/blk, 1 blk/SM -> all co-resident

    init_kernel<<<(Vdim + NTH - 1)/NTH, NTH>>>();
    lstm_rec_kernel<<<grid, NTH>>>(x, nx, embed, W_ih, W_hh, b_ih, b_hh, W_out, b_out, out);
}

// round 6
// speedup vs baseline: 1.0697x; 1.0697x over previous
#include <cuda_runtime.h>
#include <math.h>

#define Hdim 1024
#define Vdim 100000
#define Tn   64
#define KTOP 20
#define NTH  1024
#define MAXB 152

// Output layout (flattened reference pytree, float32):
//   a_hats[64], feedbacks[64], masked_probs[64*100000], hidden[64*1024], cell[64*1024]
#define OFF_AHAT 0
#define OFF_FB   Tn
#define OFF_P    (2*Tn)
#define OFF_H    ((size_t)(2*Tn) + (size_t)Tn*(size_t)Vdim)
#define OFF_C    (OFF_H + (size_t)Tn*(size_t)Hdim)

// -------- persistent scratch (device globals; no allocation) --------
__device__ float g_h[2][Hdim];
__device__ float g_c[Hdim];
__device__ float g_mask[Vdim];
__device__ float g_e[Vdim];
__device__ unsigned long long g_cand[MAXB*KTOP];
__device__ float g_Z[2];
__device__ int   g_ahat;
__device__ float g_fb;
__device__ int   g_flag;
__device__ unsigned g_barc;
__device__ unsigned g_bars;

__device__ __forceinline__ unsigned ordf(float f){
    unsigned u = __float_as_uint(f);
    return (u & 0x80000000u) ? ~u : (u | 0x80000000u);
}
__device__ __forceinline__ float sigm(float xv){ return 1.0f/(1.0f+expf(-xv)); }

__device__ __forceinline__ unsigned ldcg_u32(const unsigned* p){
    unsigned v;
    asm volatile("ld.global.cg.u32 %0, [%1];" : "=r"(v) : "l"(p));
    return v;
}
__device__ __forceinline__ int ldcg_s32(const int* p){
    int v;
    asm volatile("ld.global.cg.s32 %0, [%1];" : "=r"(v) : "l"(p));
    return v;
}

__device__ __forceinline__ unsigned long long wmax64(unsigned long long v){
    #pragma unroll
    for (int off = 16; off; off >>= 1){
        unsigned long long o = __shfl_xor_sync(0xffffffffu, v, off);
        if (o > v) v = o;
    }
    return v;
}

// descending-by-lane bitonic sort of one 64-bit key per lane (shuffle-only)
__device__ __forceinline__ unsigned long long bitonic_desc(unsigned long long key, int lane){
    unsigned long long x = ~key;            // sort ascending of ~key == descending of key
    #pragma unroll
    for (int k = 2; k <= 32; k <<= 1){
        #pragma unroll
        for (int j = k >> 1; j > 0; j >>= 1){
            unsigned long long o = __shfl_xor_sync(0xffffffffu, x, j);
            bool up      = ((lane & k) == 0);
            bool low     = ((lane & j) == 0);
            bool takeMin = (low == up);
            bool oless   = (o < x);
            x = takeMin ? (oless ? o : x) : (oless ? x : o);
        }
    }
    return ~x;
}

__device__ __forceinline__ void gridbar(volatile unsigned* s_sense){
    __syncthreads();
    if (threadIdx.x == 0){
        unsigned target = (*s_sense) ^ 1u;
        *s_sense = target;
        __threadfence();
        unsigned arrived = atomicAdd(&g_barc, 1u) + 1u;
        if (arrived == gridDim.x){
            atomicExch(&g_barc, 0u);
            __threadfence();
            atomicExch(&g_bars, target);
        } else {
            // load-poll (no atomic contention with the release write)
            while (ldcg_u32(&g_bars) != target){ __nanosleep(32); }
        }
        __threadfence();
    }
    __syncthreads();
}

__global__ void init_kernel(){
    int i = blockIdx.x*blockDim.x + threadIdx.x;
    if (i < Vdim) g_mask[i] = 1.0f;
    if (i < Hdim){ g_h[0][i]=0.f; g_h[1][i]=0.f; g_c[i]=0.f; }
    if (i == 0){
        g_Z[0]=0.f; g_Z[1]=0.f; g_ahat=0; g_fb=0.f;
        g_flag=-1; g_barc=0u; g_bars=0u;
    }
}

__global__ __launch_bounds__(NTH, 1)
void lstm_rec_kernel(const int* __restrict__ x, int nx,
                     const float* __restrict__ embed,
                     const float* __restrict__ W_ih,
                     const float* __restrict__ W_hh,
                     const float* __restrict__ b_ih,
                     const float* __restrict__ b_hh,
                     const float* __restrict__ W_out,
                     const float* __restrict__ b_out,
                     float* __restrict__ out)
{
    const int tid  = threadIdx.x;
    const int bid  = blockIdx.x;
    const int nb   = gridDim.x;
    const int lane = tid & 31;
    const int wid  = tid >> 5;

    __shared__ float s_h[Hdim];                      // h(t) staging for phase B
    __shared__ float s_x[Hdim];                      // embed[ah]*fb staging for phase A
    __shared__ float s_hp[Hdim];                     // h(t-1) staging for phase A
    __shared__ float s_gate[32];                     // per-unit gate partials (U*4 <= 32)
    __shared__ unsigned long long s_key[NTH];        // per-warp sorted keys
    __shared__ unsigned long long s_m[32*KTOP];      // block0 merge lists
    __shared__ float s_z[32];
    __shared__ int s_items[KTOP];
    __shared__ int s_hit[KTOP];
    __shared__ int s_ah;
    __shared__ float s_fb;
    __shared__ unsigned s_sense;

    if (tid == 0){ s_sense = 0u; s_ah = 0; s_fb = 0.f; }
    __syncthreads();

    // chunk rounded to multiple of 4 -> v0 16B-aligned for vector prob writes
    const int chunk = (((Vdim + nb - 1) / nb) + 3) & ~3;
    const int v0 = bid * chunk;
    int cnt = Vdim - v0; if (cnt > chunk) cnt = chunk; if (cnt < 0) cnt = 0;

    const int U = (Hdim + nb - 1) / nb;              // hidden units per block (<= 8)
    const int u0 = bid * U;

    for (int t = 0; t < Tn; ++t){
        // ============ Phase A: mask update, Z reset, distributed LSTM cell ============
        if (tid == 0){
            if (t > 0 && s_ah >= v0 && s_ah < v0 + cnt) g_mask[s_ah] = 0.f; // owner-block
            if (bid == nb - 1) g_Z[t & 1] = 0.f;   // last readers finished 2 barriers ago
        }
        {
            const float fb = s_fb;
            const int   ah = s_ah;
            s_x[tid]  = embed[(size_t)ah * Hdim + tid] * fb;
            s_hp[tid] = __ldcg(&g_h[(t & 1) ^ 1][tid]);
            __syncthreads();

            const int iu = wid >> 2;                 // local unit index
            const int gg = wid & 3;                  // gate index (i,f,g,o)
            const int j  = u0 + iu;
            if (iu < U && j < Hdim){
                const int row = gg * Hdim + j;
                const float4* __restrict__ wi4 = ((const float4*)W_ih) + (size_t)row * (Hdim/4);
                const float4* __restrict__ wh4 = ((const float4*)W_hh) + (size_t)row * (Hdim/4);
                const float4* sx4 = (const float4*)s_x;
                const float4* sh4 = (const float4*)s_hp;
                float acc = 0.f;
                #pragma unroll
                for (int q = 0; q < 8; ++q){
                    const int idx = lane + (q << 5);
                    float4 wa = wi4[idx];
                    float4 wb = wh4[idx];
                    float4 xv = sx4[idx];
                    float4 hv = sh4[idx];
                    acc += wa.x*xv.x + wa.y*xv.y + wa.z*xv.z + wa.w*xv.w;
                    acc += wb.x*hv.x + wb.y*hv.y + wb.z*hv.z + wb.w*hv.w;
                }
                #pragma unroll
                for (int off=16; off; off>>=1) acc += __shfl_down_sync(0xffffffffu, acc, off);
                if (lane == 0) s_gate[(iu << 2) | gg] = acc + b_ih[row] + b_hh[row];
            }
            __syncthreads();
            if (tid < U){
                const int j2 = u0 + tid;
                if (j2 < Hdim){
                    float gi = s_gate[(tid << 2) | 0];
                    float gf = s_gate[(tid << 2) | 1];
                    float gG = s_gate[(tid << 2) | 2];
                    float go = s_gate[(tid << 2) | 3];
                    float iv = sigm(gi), fv = sigm(gf), gv = tanhf(gG), ov = sigm(go);
                    float cv = fv * g_c[j2] + iv * gv;    // owner-block private
                    g_c[j2] = cv;
                    float hv = ov * tanhf(cv);
                    __stcg(&g_h[t & 1][j2], hv);
                    out[OFF_H + (size_t)t*Hdim + j2] = hv;
                    out[OFF_C + (size_t)t*Hdim + j2] = cv;
                }
            }
        }
        gridbar(&s_sense);

        // ============ Phase B: logits (2 rows/warp-iter), exp-sum, per-block top-20 ====
        s_h[tid] = __ldcg(&g_h[t & 1][tid]);                      // Hdim == NTH
        __syncthreads();
        const float4* s_h4 = (const float4*)s_h;

        float zacc = 0.f;
        for (int rr = wid << 1; rr < cnt; rr += 64){
            const int has1 = (rr + 1 < cnt);
            const int r1 = has1 ? rr + 1 : rr;
            const float4* __restrict__ w0p = ((const float4*)W_out) + (size_t)(v0 + rr) * (Hdim/4);
            const float4* __restrict__ w1p = ((const float4*)W_out) + (size_t)(v0 + r1) * (Hdim/4);
            float acc0 = 0.f, acc1 = 0.f;
            #pragma unroll
            for (int q = 0; q < 8; ++q){
                const int idx = lane + (q << 5);
                float4 w0 = __ldcs(w0p + idx);                    // streaming: evict-first
                float4 w1 = __ldcs(w1p + idx);
                float4 hh = s_h4[idx];
                acc0 += w0.x*hh.x + w0.y*hh.y + w0.z*hh.z + w0.w*hh.w;
                acc1 += w1.x*hh.x + w1.y*hh.y + w1.z*hh.z + w1.w*hh.w;
            }
            #pragma unroll
            for (int off=16; off; off>>=1){
                acc0 += __shfl_down_sync(0xffffffffu, acc0, off);
                acc1 += __shfl_down_sync(0xffffffffu, acc1, off);
            }
            if (lane == 0){
                const int v = v0 + rr;
                float l0 = acc0 + b_out[v];
                float e0 = expf(l0);
                g_e[v] = e0;
                zacc += e0;
                s_key[rr] = (g_mask[v] != 0.f)
                    ? ((((unsigned long long)ordf(l0)) << 32) | (unsigned long long)(~(unsigned)v))
                    : 0ULL;
                if (has1){
                    const int v1 = v + 1;
                    float l1 = acc1 + b_out[v1];
                    float e1 = expf(l1);
                    g_e[v1] = e1;
                    zacc += e1;
                    s_key[rr + 1] = (g_mask[v1] != 0.f)
                        ? ((((unsigned long long)ordf(l1)) << 32) | (unsigned long long)(~(unsigned)v1))
                        : 0ULL;
                }
            }
        }
        if (lane == 0) s_z[wid] = zacc;
        __syncthreads();
        if (wid == 0){
            float z = s_z[lane];
            #pragma unroll
            for (int off=16; off; off>>=1) z += __shfl_down_sync(0xffffffffu, z, off);
            if (lane == 0) atomicAdd(&g_Z[t & 1], z);
        }
        // per-warp bitonic sort (no syncs), then warp0 merges 32 sorted lists
        {
            unsigned long long kr = (tid < cnt) ? s_key[tid] : 0ULL;
            __syncthreads();                                      // s_key reads done
            kr = bitonic_desc(kr, lane);
            s_key[tid] = kr;                                      // lane i = i-th largest of warp
            __syncthreads();
            if (wid == 0){
                int ptr = 0;
                unsigned long long head = s_key[lane * 32];
                #pragma unroll
                for (int it = 0; it < KTOP; ++it){
                    unsigned long long m = wmax64(head);
                    unsigned ball = __ballot_sync(0xffffffffu, head == m);
                    int wl = __ffs(ball) - 1;
                    if (lane == wl){
                        ++ptr;
                        head = (ptr < 32) ? s_key[lane * 32 + ptr] : 0ULL;
                    }
                    if (lane == 0) g_cand[bid*KTOP + it] = m;
                }
            }
        }
        gridbar(&s_sense);

        // ============ Phase C: control (block0) overlapped with prob writes ============
        if (bid == 0){
            const int ncand = nb * KTOP;
            const int per = (ncand + 31) / 32;                    // <= 95
            const int base = wid * per;
            int mycnt = ncand - base;
            if (mycnt > per) mycnt = per; if (mycnt < 0) mycnt = 0;
            unsigned long long c0 = (lane      < mycnt) ? __ldcg(&g_cand[base + lane     ]) : 0ULL;
            unsigned long long c1 = (lane + 32 < mycnt) ? __ldcg(&g_cand[base + lane + 32]) : 0ULL;
            unsigned long long c2 = (lane + 64 < mycnt) ? __ldcg(&g_cand[base + lane + 64]) : 0ULL;
            #pragma unroll
            for (int it = 0; it < KTOP; ++it){                    // per-warp top-20 (shuffle-only)
                unsigned long long loc = c0;
                if (c1 > loc) loc = c1;
                if (c2 > loc) loc = c2;
                unsigned long long m = wmax64(loc);
                if      (c0 == m) c0 = 0ULL;
                else if (c1 == m) c1 = 0ULL;
                else if (c2 == m) c2 = 0ULL;
                if (lane == 0) s_m[wid*KTOP + it] = m;
            }
            __syncthreads();
            if (wid == 0){                                        // 32-way merge of sorted lists
                int ptr = 0;
                unsigned long long head = s_m[lane * KTOP];
                #pragma unroll
                for (int it = 0; it < KTOP; ++it){
                    unsigned long long m = wmax64(head);
                    unsigned ball = __ballot_sync(0xffffffffu, head == m);
                    int wl = __ffs(ball) - 1;
                    if (lane == wl){
                        ++ptr;
                        head = (ptr < KTOP) ? s_m[lane * KTOP + ptr] : 0ULL;
                    }
                    if (lane == 0) s_items[it] = (int)(~(unsigned)(m & 0xffffffffu));
                }
            }
            __syncthreads();
            // parallel hit check: one warp per candidate, lanes stride x[]
            if (wid < KTOP){
                const int want = s_items[wid] + 1;                // 1-indexed compare
                int h = 0;
                for (int jx = lane; jx < nx; jx += 32) h |= (x[jx] == want);
                h = __any_sync(0xffffffffu, h);
                if (lane == 0) s_hit[wid] = h;
            }
            __syncthreads();
            if (tid == 0){
                int card = 0, first = -1;
                #pragma unroll
                for (int k2 = 0; k2 < KTOP; ++k2){
                    if (s_hit[k2]){ ++card; if (first < 0) first = k2; }
                }
                const int ah = (card > 0) ? s_items[first] : s_items[0];
                const float fbn = (card > 0) ? 1.f : -1.f;
                s_ah = ah; s_fb = fbn;
                g_ahat = ah; g_fb = fbn;
                out[OFF_AHAT + t] = (float)ah;
                out[OFF_FB + t]   = fbn;
                __threadfence();
                atomicExch(&g_flag, t);                           // publish step-t control
            }
        }
        // all blocks: masked-prob writes (vectorized; overlaps block0's control)
        {
            const float Zinv = 1.0f / __ldcg(&g_Z[t & 1]);
            const int cnt4 = cnt >> 2;                            // v0 16B-aligned by chunk pad
            const float4* e4 = (const float4*)(g_e + v0);
            const float4* m4 = (const float4*)(g_mask + v0);
            float4* o4 = (float4*)(out + OFF_P + (size_t)t*Vdim + v0);
            for (int r = tid; r < cnt4; r += NTH){
                float4 e = e4[r];
                float4 m = m4[r];
                float4 p = make_float4(e.x*Zinv*m.x, e.y*Zinv*m.y, e.z*Zinv*m.z, e.w*Zinv*m.w);
                __stcs(o4 + r, p);
            }
            for (int r = (cnt4 << 2) + tid; r < cnt; r += NTH){   // tail (robustness)
                const int v = v0 + r;
                __stcs(&out[OFF_P + (size_t)t*Vdim + v], g_e[v] * Zinv * g_mask[v]);
            }
        }
        if (bid != 0 && tid == 0){
            while (ldcg_s32(&g_flag) < t){ __nanosleep(32); }     // load-poll
            __threadfence();
            s_ah = __ldcg(&g_ahat);
            s_fb = __ldcg(&g_fb);
        }
        __syncthreads();                                          // s_ah/s_fb block-visible
    }
}

extern "C" void kernel_launch(void* const* d_in, const int* in_sizes, int n_in,
                              void* d_out, int out_size)
{
    const int*   x     = (const int*)  d_in[0];
    const float* embed = (const float*)d_in[1];
    const float* W_ih  = (const float*)d_in[2];
    const float* W_hh  = (const float*)d_in[3];
    const float* b_ih  = (const float*)d_in[4];
    const float* b_hh  = (const float*)d_in[5];
    const float* W_out = (const float*)d_in[6];
    const float* b_out = (const float*)d_in[7];
    float* out = (float*)d_out;
    const int nx = in_sizes[0];

    int dev = 0;
    cudaGetDevice(&dev);
    int sm = 148;
    cudaDeviceGetAttribute(&sm, cudaDevAttrMultiProcessorCount, dev);
    int grid = sm < MAXB ? sm : MAXB;   // 1024 thr/blk, 1 blk/SM -> all co-resident

    init_kernel<<<(Vdim + NTH - 1)/NTH, NTH>>>();
    lstm_rec_kernel<<<grid, NTH>>>(x, nx, embed, W_ih, W_hh, b_ih, b_hh, W_out, b_out, out);
}

// round 16
// speedup vs baseline: 1.5302x; 1.4305x over previous
#include <cuda_runtime.h>
#include <cuda_fp16.h>
#include <math.h>

#define Hdim 1024
#define Vdim 100000
#define Tn   64
#define KTOP 20
#define NTH  1024
#define MAXB 152

// Output layout (flattened reference pytree, float32):
//   a_hats[64], feedbacks[64], masked_probs[64*100000], hidden[64*1024], cell[64*1024]
#define OFF_AHAT 0
#define OFF_FB   Tn
#define OFF_P    (2*Tn)
#define OFF_H    ((size_t)(2*Tn) + (size_t)Tn*(size_t)Vdim)
#define OFF_C    (OFF_H + (size_t)Tn*(size_t)Hdim)

// -------- persistent scratch (device globals; no allocation) --------
__device__ __align__(16) __half g_wout[(size_t)Vdim * Hdim];   // fp16 copy of W_out (204.8MB)
__device__ float g_h[2][Hdim];
__device__ float g_c[Hdim];
__device__ float g_mask[Vdim];
__device__ float g_e[Vdim];
__device__ unsigned long long g_cand[MAXB*KTOP];
__device__ float g_Z[2];
__device__ int   g_ahat;
__device__ float g_fb;
__device__ int   g_flag;
__device__ unsigned g_barc;
__device__ unsigned g_bars;

__device__ __forceinline__ unsigned ordf(float f){
    unsigned u = __float_as_uint(f);
    return (u & 0x80000000u) ? ~u : (u | 0x80000000u);
}
__device__ __forceinline__ float sigm(float xv){ return 1.0f/(1.0f+expf(-xv)); }

__device__ __forceinline__ unsigned ldcg_u32(const unsigned* p){
    unsigned v;
    asm volatile("ld.global.cg.u32 %0, [%1];" : "=r"(v) : "l"(p));
    return v;
}
__device__ __forceinline__ int ldcg_s32(const int* p){
    int v;
    asm volatile("ld.global.cg.s32 %0, [%1];" : "=r"(v) : "l"(p));
    return v;
}

// dot of 8 fp16 weights (packed in a float4) with 8 fp32 h values
__device__ __forceinline__ float dot8(float4 w, float4 ha, float4 hb){
    const __half2* h2 = reinterpret_cast<const __half2*>(&w);
    float2 f0 = __half22float2(h2[0]);
    float2 f1 = __half22float2(h2[1]);
    float2 f2 = __half22float2(h2[2]);
    float2 f3 = __half22float2(h2[3]);
    return f0.x*ha.x + f0.y*ha.y + f1.x*ha.z + f1.y*ha.w
         + f2.x*hb.x + f2.y*hb.y + f3.x*hb.z + f3.y*hb.w;
}

__device__ __forceinline__ unsigned long long wmax64(unsigned long long v){
    #pragma unroll
    for (int off = 16; off; off >>= 1){
        unsigned long long o = __shfl_xor_sync(0xffffffffu, v, off);
        if (o > v) v = o;
    }
    return v;
}

// descending-by-lane bitonic sort of one 64-bit key per lane (shuffle-only)
__device__ __forceinline__ unsigned long long bitonic_desc(unsigned long long key, int lane){
    unsigned long long x = ~key;            // sort ascending of ~key == descending of key
    #pragma unroll
    for (int k = 2; k <= 32; k <<= 1){
        #pragma unroll
        for (int j = k >> 1; j > 0; j >>= 1){
            unsigned long long o = __shfl_xor_sync(0xffffffffu, x, j);
            bool up      = ((lane & k) == 0);
            bool low     = ((lane & j) == 0);
            bool takeMin = (low == up);
            bool oless   = (o < x);
            x = takeMin ? (oless ? o : x) : (oless ? x : o);
        }
    }
    return ~x;
}

__device__ __forceinline__ void gridbar(volatile unsigned* s_sense){
    __syncthreads();
    if (threadIdx.x == 0){
        unsigned target = (*s_sense) ^ 1u;
        *s_sense = target;
        __threadfence();
        unsigned arrived = atomicAdd(&g_barc, 1u) + 1u;
        if (arrived == gridDim.x){
            atomicExch(&g_barc, 0u);
            __threadfence();
            atomicExch(&g_bars, target);
        } else {
            while (ldcg_u32(&g_bars) != target){ __nanosleep(32); }
        }
        __threadfence();
    }
    __syncthreads();
}

__global__ void init_kernel(){
    int i = blockIdx.x*blockDim.x + threadIdx.x;
    if (i < Vdim) g_mask[i] = 1.0f;
    if (i < Hdim){ g_h[0][i]=0.f; g_h[1][i]=0.f; g_c[i]=0.f; }
    if (i == 0){
        g_Z[0]=0.f; g_Z[1]=0.f; g_ahat=0; g_fb=0.f;
        g_flag=-1; g_barc=0u; g_bars=0u;
    }
}

// convert W_out fp32 -> fp16 (8 elements per thread-iteration)
__global__ void conv_wout_kernel(const float* __restrict__ W_out){
    const size_t n8 = (size_t)Vdim * Hdim / 8;
    const size_t stride = (size_t)gridDim.x * blockDim.x;
    for (size_t i = (size_t)blockIdx.x*blockDim.x + threadIdx.x; i < n8; i += stride){
        float4 a = __ldcs(((const float4*)W_out) + 2*i);
        float4 b = __ldcs(((const float4*)W_out) + 2*i + 1);
        float4 packed;
        __half2* p2 = reinterpret_cast<__half2*>(&packed);
        p2[0] = __floats2half2_rn(a.x, a.y);
        p2[1] = __floats2half2_rn(a.z, a.w);
        p2[2] = __floats2half2_rn(b.x, b.y);
        p2[3] = __floats2half2_rn(b.z, b.w);
        __stcs(((float4*)g_wout) + i, packed);
    }
}

__global__ __launch_bounds__(NTH, 1)
void lstm_rec_kernel(const int* __restrict__ x, int nx,
                     const float* __restrict__ embed,
                     const float* __restrict__ W_ih,
                     const float* __restrict__ W_hh,
                     const float* __restrict__ b_ih,
                     const float* __restrict__ b_hh,
                     const float* __restrict__ b_out,
                     float* __restrict__ out)
{
    const int tid  = threadIdx.x;
    const int bid  = blockIdx.x;
    const int nb   = gridDim.x;
    const int lane = tid & 31;
    const int wid  = tid >> 5;

    __shared__ float s_h[Hdim];                      // h(t) staging for phase B
    __shared__ float s_x[Hdim];                      // embed[ah]*fb staging for phase A
    __shared__ float s_hp[Hdim];                     // h(t-1) staging for phase A
    __shared__ float s_gate[32];                     // per-unit gate partials (U*4 <= 32)
    __shared__ unsigned long long s_key[NTH];        // per-warp sorted keys
    __shared__ unsigned long long s_m[32*KTOP];      // block0 merge lists
    __shared__ float s_z[32];
    __shared__ int s_items[KTOP];
    __shared__ int s_hit[KTOP];
    __shared__ int s_ah;
    __shared__ float s_fb;
    __shared__ unsigned s_sense;

    if (tid == 0){ s_sense = 0u; s_ah = 0; s_fb = 0.f; }
    __syncthreads();

    // chunk rounded to multiple of 4 -> cnt always a multiple of 4, v0 16B-aligned
    const int chunk = (((Vdim + nb - 1) / nb) + 3) & ~3;
    const int v0 = bid * chunk;
    int cnt = Vdim - v0; if (cnt > chunk) cnt = chunk; if (cnt < 0) cnt = 0;

    const int U = (Hdim + nb - 1) / nb;              // hidden units per block (<= 8)
    const int u0 = bid * U;

    for (int t = 0; t < Tn; ++t){
        // ============ Phase A: mask update, Z reset, distributed LSTM cell ============
        if (tid == 0){
            if (t > 0 && s_ah >= v0 && s_ah < v0 + cnt) g_mask[s_ah] = 0.f; // owner-block
            if (bid == nb - 1) g_Z[t & 1] = 0.f;   // last readers finished 2 barriers ago
        }
        {
            const float fb = s_fb;
            const int   ah = s_ah;
            s_x[tid]  = embed[(size_t)ah * Hdim + tid] * fb;
            s_hp[tid] = __ldcg(&g_h[(t & 1) ^ 1][tid]);
            __syncthreads();

            const int iu = wid >> 2;                 // local unit index
            const int gg = wid & 3;                  // gate index (i,f,g,o)
            const int j  = u0 + iu;
            if (iu < U && j < Hdim){
                const int row = gg * Hdim + j;
                const float4* __restrict__ wi4 = ((const float4*)W_ih) + (size_t)row * (Hdim/4);
                const float4* __restrict__ wh4 = ((const float4*)W_hh) + (size_t)row * (Hdim/4);
                const float4* sx4 = (const float4*)s_x;
                const float4* sh4 = (const float4*)s_hp;
                float acc = 0.f;
                #pragma unroll
                for (int q = 0; q < 8; ++q){
                    const int idx = lane + (q << 5);
                    float4 wa = wi4[idx];
                    float4 wb = wh4[idx];
                    float4 xv = sx4[idx];
                    float4 hv = sh4[idx];
                    acc += wa.x*xv.x + wa.y*xv.y + wa.z*xv.z + wa.w*xv.w;
                    acc += wb.x*hv.x + wb.y*hv.y + wb.z*hv.z + wb.w*hv.w;
                }
                #pragma unroll
                for (int off=16; off; off>>=1) acc += __shfl_down_sync(0xffffffffu, acc, off);
                if (lane == 0) s_gate[(iu << 2) | gg] = acc + b_ih[row] + b_hh[row];
            }
            __syncthreads();
            if (tid < U){
                const int j2 = u0 + tid;
                if (j2 < Hdim){
                    float gi = s_gate[(tid << 2) | 0];
                    float gf = s_gate[(tid << 2) | 1];
                    float gG = s_gate[(tid << 2) | 2];
                    float go = s_gate[(tid << 2) | 3];
                    float iv = sigm(gi), fv = sigm(gf), gv = tanhf(gG), ov = sigm(go);
                    float cv = fv * g_c[j2] + iv * gv;    // owner-block private
                    g_c[j2] = cv;
                    float hv = ov * tanhf(cv);
                    __stcg(&g_h[t & 1][j2], hv);
                    out[OFF_H + (size_t)t*Hdim + j2] = hv;
                    out[OFF_C + (size_t)t*Hdim + j2] = cv;
                }
            }
        }
        gridbar(&s_sense);

        // ============ Phase B: fp16 logits (4 rows/warp-iter), exp-sum, top-20 ==========
        s_h[tid] = __ldcg(&g_h[t & 1][tid]);                      // Hdim == NTH
        __syncthreads();
        const float4* s_h4 = (const float4*)s_h;

        float zacc = 0.f;
        for (int rr = wid << 2; rr < cnt; rr += 128){             // cnt % 4 == 0
            const __half* base = g_wout + (size_t)(v0 + rr) * Hdim;
            const float4* __restrict__ w0p = (const float4*)(base);
            const float4* __restrict__ w1p = (const float4*)(base + Hdim);
            const float4* __restrict__ w2p = (const float4*)(base + 2*Hdim);
            const float4* __restrict__ w3p = (const float4*)(base + 3*Hdim);
            float a0=0.f, a1=0.f, a2=0.f, a3=0.f;
            #pragma unroll
            for (int c = 0; c < 4; ++c){
                const int idx = lane + (c << 5);                  // float4 idx in row (0..127)
                float4 ha = s_h4[idx*2];
                float4 hb = s_h4[idx*2 + 1];
                a0 += dot8(__ldcs(w0p + idx), ha, hb);
                a1 += dot8(__ldcs(w1p + idx), ha, hb);
                a2 += dot8(__ldcs(w2p + idx), ha, hb);
                a3 += dot8(__ldcs(w3p + idx), ha, hb);
            }
            #pragma unroll
            for (int off=16; off; off>>=1){
                a0 += __shfl_down_sync(0xffffffffu, a0, off);
                a1 += __shfl_down_sync(0xffffffffu, a1, off);
                a2 += __shfl_down_sync(0xffffffffu, a2, off);
                a3 += __shfl_down_sync(0xffffffffu, a3, off);
            }
            if (lane == 0){
                const int v = v0 + rr;
                float l[4] = {a0, a1, a2, a3};
                #pragma unroll
                for (int k2 = 0; k2 < 4; ++k2){
                    float lv = l[k2] + b_out[v + k2];
                    float ev = expf(lv);
                    g_e[v + k2] = ev;
                    zacc += ev;
                    s_key[rr + k2] = (g_mask[v + k2] != 0.f)
                        ? ((((unsigned long long)ordf(lv)) << 32)
                           | (unsigned long long)(~(unsigned)(v + k2)))
                        : 0ULL;
                }
            }
        }
        if (lane == 0) s_z[wid] = zacc;
        __syncthreads();
        if (wid == 0){
            float z = s_z[lane];
            #pragma unroll
            for (int off=16; off; off>>=1) z += __shfl_down_sync(0xffffffffu, z, off);
            if (lane == 0) atomicAdd(&g_Z[t & 1], z);
        }
        // per-warp bitonic sort (no syncs), then warp0 merges 32 sorted lists
        {
            unsigned long long kr = (tid < cnt) ? s_key[tid] : 0ULL;
            __syncthreads();                                      // s_key reads done
            kr = bitonic_desc(kr, lane);
            s_key[tid] = kr;                                      // lane i = i-th largest of warp
            __syncthreads();
            if (wid == 0){
                int ptr = 0;
                unsigned long long head = s_key[lane * 32];
                #pragma unroll
                for (int it = 0; it < KTOP; ++it){
                    unsigned long long m = wmax64(head);
                    unsigned ball = __ballot_sync(0xffffffffu, head == m);
                    int wl = __ffs(ball) - 1;
                    if (lane == wl){
                        ++ptr;
                        head = (ptr < 32) ? s_key[lane * 32 + ptr] : 0ULL;
                    }
                    if (lane == 0) g_cand[bid*KTOP + it] = m;
                }
            }
        }
        gridbar(&s_sense);

        // ============ Phase C: control (block0) overlapped with prob writes ============
        if (bid == 0){
            const int ncand = nb * KTOP;
            const int per = (ncand + 31) / 32;                    // <= 95
            const int base = wid * per;
            int mycnt = ncand - base;
            if (mycnt > per) mycnt = per; if (mycnt < 0) mycnt = 0;
            unsigned long long c0 = (lane      < mycnt) ? __ldcg(&g_cand[base + lane     ]) : 0ULL;
            unsigned long long c1 = (lane + 32 < mycnt) ? __ldcg(&g_cand[base + lane + 32]) : 0ULL;
            unsigned long long c2 = (lane + 64 < mycnt) ? __ldcg(&g_cand[base + lane + 64]) : 0ULL;
            #pragma unroll
            for (int it = 0; it < KTOP; ++it){                    // per-warp top-20 (shuffle-only)
                unsigned long long loc = c0;
                if (c1 > loc) loc = c1;
                if (c2 > loc) loc = c2;
                unsigned long long m = wmax64(loc);
                if      (c0 == m) c0 = 0ULL;
                else if (c1 == m) c1 = 0ULL;
                else if (c2 == m) c2 = 0ULL;
                if (lane == 0) s_m[wid*KTOP + it] = m;
            }
            __syncthreads();
            if (wid == 0){                                        // 32-way merge of sorted lists
                int ptr = 0;
                unsigned long long head = s_m[lane * KTOP];
                #pragma unroll
                for (int it = 0; it < KTOP; ++it){
                    unsigned long long m = wmax64(head);
                    unsigned ball = __ballot_sync(0xffffffffu, head == m);
                    int wl = __ffs(ball) - 1;
                    if (lane == wl){
                        ++ptr;
                        head = (ptr < KTOP) ? s_m[lane * KTOP + ptr] : 0ULL;
                    }
                    if (lane == 0) s_items[it] = (int)(~(unsigned)(m & 0xffffffffu));
                }
            }
            __syncthreads();
            // parallel hit check: one warp per candidate, lanes stride x[]
            if (wid < KTOP){
                const int want = s_items[wid] + 1;                // 1-indexed compare
                int h = 0;
                for (int jx = lane; jx < nx; jx += 32) h |= (x[jx] == want);
                h = __any_sync(0xffffffffu, h);
                if (lane == 0) s_hit[wid] = h;
            }
            __syncthreads();
            if (tid == 0){
                int card = 0, first = -1;
                #pragma unroll
                for (int k2 = 0; k2 < KTOP; ++k2){
                    if (s_hit[k2]){ ++card; if (first < 0) first = k2; }
                }
                const int ah = (card > 0) ? s_items[first] : s_items[0];
                const float fbn = (card > 0) ? 1.f : -1.f;
                s_ah = ah; s_fb = fbn;
                g_ahat = ah; g_fb = fbn;
                out[OFF_AHAT + t] = (float)ah;
                out[OFF_FB + t]   = fbn;
                __threadfence();
                atomicExch(&g_flag, t);                           // publish step-t control
            }
        }
        // all blocks: masked-prob writes (vectorized; overlaps block0's control)
        {
            const float Zinv = 1.0f / __ldcg(&g_Z[t & 1]);
            const int cnt4 = cnt >> 2;                            // v0 16B-aligned by chunk pad
            const float4* e4 = (const float4*)(g_e + v0);
            const float4* m4 = (const float4*)(g_mask + v0);
            float4* o4 = (float4*)(out + OFF_P + (size_t)t*Vdim + v0);
            for (int r = tid; r < cnt4; r += NTH){
                float4 e = e4[r];
                float4 m = m4[r];
                float4 p = make_float4(e.x*Zinv*m.x, e.y*Zinv*m.y, e.z*Zinv*m.z, e.w*Zinv*m.w);
                __stcs(o4 + r, p);
            }
        }
        if (bid != 0 && tid == 0){
            while (ldcg_s32(&g_flag) < t){ __nanosleep(32); }     // load-poll
            __threadfence();
            s_ah = __ldcg(&g_ahat);
            s_fb = __ldcg(&g_fb);
        }
        __syncthreads();                                          // s_ah/s_fb block-visible
    }
}

extern "C" void kernel_launch(void* const* d_in, const int* in_sizes, int n_in,
                              void* d_out, int out_size)
{
    const int*   x     = (const int*)  d_in[0];
    const float* embed = (const float*)d_in[1];
    const float* W_ih  = (const float*)d_in[2];
    const float* W_hh  = (const float*)d_in[3];
    const float* b_ih  = (const float*)d_in[4];
    const float* b_hh  = (const float*)d_in[5];
    const float* W_out = (const float*)d_in[6];
    const float* b_out = (const float*)d_in[7];
    float* out = (float*)d_out;
    const int nx = in_sizes[0];

    int dev = 0;
    cudaGetDevice(&dev);
    int sm = 148;
    cudaDeviceGetAttribute(&sm, cudaDevAttrMultiProcessorCount, dev);
    int grid = sm < MAXB ? sm : MAXB;   // 1024 thr/blk, 1 blk/SM -> all co-resident

    init_kernel<<<(Vdim + NTH - 1)/NTH, NTH>>>();
    conv_wout_kernel<<<grid * 8, 256>>>(W_out);
    lstm_rec_kernel<<<grid, NTH>>>(x, nx, embed, W_ih, W_hh, b_ih, b_hh, b_out, out);
}

// round 17
// speedup vs baseline: 1.5883x; 1.0380x over previous
#include <cuda_runtime.h>
#include <math.h>

#define Hdim 1024
#define Vdim 100000
#define Tn   64
#define KTOP 20
#define KCAND 28
#define NTH  1024
#define MAXB 152

// Output layout (flattened reference pytree, float32):
//   a_hats[64], feedbacks[64], masked_probs[64*100000], hidden[64*1024], cell[64*1024]
#define OFF_AHAT 0
#define OFF_FB   Tn
#define OFF_P    (2*Tn)
#define OFF_H    ((size_t)(2*Tn) + (size_t)Tn*(size_t)Vdim)
#define OFF_C    (OFF_H + (size_t)Tn*(size_t)Hdim)

// -------- persistent scratch (device globals; no allocation) --------
__device__ __align__(16) signed char g_wq[(size_t)Vdim * Hdim];  // int8 W_out (102.4MB)
__device__ float g_wscale[Vdim];                                 // per-row scales
__device__ float g_h[2][Hdim];
__device__ float g_c[Hdim];
__device__ float g_mask[Vdim];
__device__ float g_e[Vdim];
__device__ unsigned long long g_cand[MAXB*KTOP];
__device__ float g_Z[2];
__device__ int   g_ahat;
__device__ float g_fb;
__device__ int   g_flag;
__device__ unsigned g_barc;
__device__ unsigned g_bars;

__device__ __forceinline__ unsigned ordf(float f){
    unsigned u = __float_as_uint(f);
    return (u & 0x80000000u) ? ~u : (u | 0x80000000u);
}
__device__ __forceinline__ float sigm(float xv){ return 1.0f/(1.0f+expf(-xv)); }

__device__ __forceinline__ unsigned ldcg_u32(const unsigned* p){
    unsigned v;
    asm volatile("ld.global.cg.u32 %0, [%1];" : "=r"(v) : "l"(p));
    return v;
}
__device__ __forceinline__ int ldcg_s32(const int* p){
    int v;
    asm volatile("ld.global.cg.s32 %0, [%1];" : "=r"(v) : "l"(p));
    return v;
}

// dot of 4 packed int8 weights with 4 fp32 h values
__device__ __forceinline__ float dotb4(int w, float4 h){
    return (float)((signed char)(w      )) * h.x
         + (float)((signed char)(w >>  8)) * h.y
         + (float)((signed char)(w >> 16)) * h.z
         + (float)((signed char)(w >> 24)) * h.w;
}

__device__ __forceinline__ unsigned long long wmax64(unsigned long long v){
    #pragma unroll
    for (int off = 16; off; off >>= 1){
        unsigned long long o = __shfl_xor_sync(0xffffffffu, v, off);
        if (o > v) v = o;
    }
    return v;
}

// descending-by-lane bitonic sort of one 64-bit key per lane (shuffle-only)
__device__ __forceinline__ unsigned long long bitonic_desc(unsigned long long key, int lane){
    unsigned long long x = ~key;            // sort ascending of ~key == descending of key
    #pragma unroll
    for (int k = 2; k <= 32; k <<= 1){
        #pragma unroll
        for (int j = k >> 1; j > 0; j >>= 1){
            unsigned long long o = __shfl_xor_sync(0xffffffffu, x, j);
            bool up      = ((lane & k) == 0);
            bool low     = ((lane & j) == 0);
            bool takeMin = (low == up);
            bool oless   = (o < x);
            x = takeMin ? (oless ? o : x) : (oless ? x : o);
        }
    }
    return ~x;
}

__device__ __forceinline__ void gridbar(volatile unsigned* s_sense){
    __syncthreads();
    if (threadIdx.x == 0){
        unsigned target = (*s_sense) ^ 1u;
        *s_sense = target;
        __threadfence();
        unsigned arrived = atomicAdd(&g_barc, 1u) + 1u;
        if (arrived == gridDim.x){
            atomicExch(&g_barc, 0u);
            __threadfence();
            atomicExch(&g_bars, target);
        } else {
            while (ldcg_u32(&g_bars) != target){ __nanosleep(32); }
        }
        __threadfence();
    }
    __syncthreads();
}

__global__ void init_kernel(){
    int i = blockIdx.x*blockDim.x + threadIdx.x;
    if (i < Vdim) g_mask[i] = 1.0f;
    if (i < Hdim){ g_h[0][i]=0.f; g_h[1][i]=0.f; g_c[i]=0.f; }
    if (i == 0){
        g_Z[0]=0.f; g_Z[1]=0.f; g_ahat=0; g_fb=0.f;
        g_flag=-1; g_barc=0u; g_bars=0u;
    }
}

// quantize W_out fp32 -> int8 with per-row absmax scale (one warp per row)
__global__ void quant_wout_kernel(const float* __restrict__ W_out){
    const int lane = threadIdx.x & 31;
    const int gw = blockIdx.x * (blockDim.x >> 5) + (threadIdx.x >> 5);
    const int nw = gridDim.x * (blockDim.x >> 5);
    for (int v = gw; v < Vdim; v += nw){
        const float4* wr = ((const float4*)W_out) + (size_t)v * (Hdim/4);
        float4 f[8];
        float mx = 0.f;
        #pragma unroll
        for (int c = 0; c < 8; ++c){
            f[c] = __ldcs(wr + lane + (c<<5));
            mx = fmaxf(mx, fmaxf(fmaxf(fabsf(f[c].x), fabsf(f[c].y)),
                                 fmaxf(fabsf(f[c].z), fabsf(f[c].w))));
        }
        #pragma unroll
        for (int off=16; off; off>>=1) mx = fmaxf(mx, __shfl_xor_sync(0xffffffffu, mx, off));
        mx = fmaxf(mx, 1e-30f);
        const float inv = 127.f / mx;
        char4* row = (char4*)(g_wq + (size_t)v * Hdim);
        #pragma unroll
        for (int c = 0; c < 8; ++c){
            char4 q;
            q.x = (signed char)__float2int_rn(f[c].x * inv);
            q.y = (signed char)__float2int_rn(f[c].y * inv);
            q.z = (signed char)__float2int_rn(f[c].z * inv);
            q.w = (signed char)__float2int_rn(f[c].w * inv);
            row[lane + (c<<5)] = q;
        }
        if (lane == 0) g_wscale[v] = mx / 127.f;
    }
}

__global__ __launch_bounds__(NTH, 1)
void lstm_rec_kernel(const int* __restrict__ x, int nx,
                     const float* __restrict__ embed,
                     const float* __restrict__ W_ih,
                     const float* __restrict__ W_hh,
                     const float* __restrict__ b_ih,
                     const float* __restrict__ b_hh,
                     const float* __restrict__ W_out,
                     const float* __restrict__ b_out,
                     float* __restrict__ out)
{
    const int tid  = threadIdx.x;
    const int bid  = blockIdx.x;
    const int nb   = gridDim.x;
    const int lane = tid & 31;
    const int wid  = tid >> 5;

    __shared__ float s_h[Hdim];                      // h(t) staging for phase B
    __shared__ float s_x[Hdim];                      // embed[ah]*fb staging for phase A
    __shared__ float s_hp[Hdim];                     // h(t-1) staging for phase A
    __shared__ float s_gate[32];                     // per-unit gate partials (U*4 <= 32)
    __shared__ unsigned long long s_key[NTH];        // per-warp sorted keys
    __shared__ unsigned long long s_m[32*KTOP];      // candidates + block0 merge lists
    __shared__ float s_z[32];
    __shared__ int s_items[KTOP];
    __shared__ int s_hit[KTOP];
    __shared__ int s_ah;
    __shared__ float s_fb;
    __shared__ unsigned s_sense;

    if (tid == 0){ s_sense = 0u; s_ah = 0; s_fb = 0.f; }
    __syncthreads();

    // chunk rounded to multiple of 4 -> cnt always a multiple of 4, v0 16B-aligned
    const int chunk = (((Vdim + nb - 1) / nb) + 3) & ~3;
    const int v0 = bid * chunk;
    int cnt = Vdim - v0; if (cnt > chunk) cnt = chunk; if (cnt < 0) cnt = 0;

    const int U = (Hdim + nb - 1) / nb;              // hidden units per block (<= 8)
    const int u0 = bid * U;

    for (int t = 0; t < Tn; ++t){
        // ============ Phase A: mask update, Z reset, distributed LSTM cell ============
        if (tid == 0){
            if (t > 0 && s_ah >= v0 && s_ah < v0 + cnt) g_mask[s_ah] = 0.f; // owner-block
            if (bid == nb - 1) g_Z[t & 1] = 0.f;   // last readers finished 2 barriers ago
        }
        {
            const float fb = s_fb;
            const int   ah = s_ah;
            s_x[tid]  = embed[(size_t)ah * Hdim + tid] * fb;
            s_hp[tid] = __ldcg(&g_h[(t & 1) ^ 1][tid]);
            __syncthreads();

            const int iu = wid >> 2;                 // local unit index
            const int gg = wid & 3;                  // gate index (i,f,g,o)
            const int j  = u0 + iu;
            if (iu < U && j < Hdim){
                const int row = gg * Hdim + j;
                const float4* __restrict__ wi4 = ((const float4*)W_ih) + (size_t)row * (Hdim/4);
                const float4* __restrict__ wh4 = ((const float4*)W_hh) + (size_t)row * (Hdim/4);
                const float4* sx4 = (const float4*)s_x;
                const float4* sh4 = (const float4*)s_hp;
                float acc = 0.f;
                #pragma unroll
                for (int q = 0; q < 8; ++q){
                    const int idx = lane + (q << 5);
                    float4 wa = wi4[idx];
                    float4 wb = wh4[idx];
                    float4 xv = sx4[idx];
                    float4 hv = sh4[idx];
                    acc += wa.x*xv.x + wa.y*xv.y + wa.z*xv.z + wa.w*xv.w;
                    acc += wb.x*hv.x + wb.y*hv.y + wb.z*hv.z + wb.w*hv.w;
                }
                #pragma unroll
                for (int off=16; off; off>>=1) acc += __shfl_down_sync(0xffffffffu, acc, off);
                if (lane == 0) s_gate[(iu << 2) | gg] = acc + b_ih[row] + b_hh[row];
            }
            __syncthreads();
            if (tid < U){
                const int j2 = u0 + tid;
                if (j2 < Hdim){
                    float gi = s_gate[(tid << 2) | 0];
                    float gf = s_gate[(tid << 2) | 1];
                    float gG = s_gate[(tid << 2) | 2];
                    float go = s_gate[(tid << 2) | 3];
                    float iv = sigm(gi), fv = sigm(gf), gv = tanhf(gG), ov = sigm(go);
                    float cv = fv * g_c[j2] + iv * gv;    // owner-block private
                    g_c[j2] = cv;
                    float hv = ov * tanhf(cv);
                    __stcg(&g_h[t & 1][j2], hv);
                    out[OFF_H + (size_t)t*Hdim + j2] = hv;
                    out[OFF_C + (size_t)t*Hdim + j2] = cv;
                }
            }
        }
        gridbar(&s_sense);

        // ============ Phase B: int8 logits (4 rows/warp-iter), exp-sum, top-K ==========
        s_h[tid] = __ldcg(&g_h[t & 1][tid]);                      // Hdim == NTH
        __syncthreads();
        const float4* s_h4 = (const float4*)s_h;

        float zacc = 0.f;
        for (int rr = wid << 2; rr < cnt; rr += 128){             // cnt % 4 == 0
            const int4* q0 = ((const int4*)g_wq) + (size_t)(v0 + rr) * (Hdim/16);
            const int4* q1 = q0 + (Hdim/16);
            const int4* q2 = q0 + 2*(Hdim/16);
            const int4* q3 = q0 + 3*(Hdim/16);
            float a0=0.f, a1=0.f, a2=0.f, a3=0.f;
            #pragma unroll
            for (int c = 0; c < 2; ++c){
                const int idx = lane + (c << 5);                  // int4 idx in row (0..63)
                int4 w0 = __ldcs(q0 + idx);
                int4 w1 = __ldcs(q1 + idx);
                int4 w2 = __ldcs(q2 + idx);
                int4 w3 = __ldcs(q3 + idx);
                float4 hA = s_h4[4*idx], hB = s_h4[4*idx+1];
                float4 hC = s_h4[4*idx+2], hD = s_h4[4*idx+3];
                a0 += dotb4(w0.x,hA) + dotb4(w0.y,hB) + dotb4(w0.z,hC) + dotb4(w0.w,hD);
                a1 += dotb4(w1.x,hA) + dotb4(w1.y,hB) + dotb4(w1.z,hC) + dotb4(w1.w,hD);
                a2 += dotb4(w2.x,hA) + dotb4(w2.y,hB) + dotb4(w2.z,hC) + dotb4(w2.w,hD);
                a3 += dotb4(w3.x,hA) + dotb4(w3.y,hB) + dotb4(w3.z,hC) + dotb4(w3.w,hD);
            }
            #pragma unroll
            for (int off=16; off; off>>=1){
                a0 += __shfl_down_sync(0xffffffffu, a0, off);
                a1 += __shfl_down_sync(0xffffffffu, a1, off);
                a2 += __shfl_down_sync(0xffffffffu, a2, off);
                a3 += __shfl_down_sync(0xffffffffu, a3, off);
            }
            if (lane == 0){
                const int v = v0 + rr;
                float l[4];
                l[0] = a0 * g_wscale[v];
                l[1] = a1 * g_wscale[v+1];
                l[2] = a2 * g_wscale[v+2];
                l[3] = a3 * g_wscale[v+3];
                #pragma unroll
                for (int k2 = 0; k2 < 4; ++k2){
                    float lv = l[k2] + b_out[v + k2];
                    float ev = expf(lv);
                    g_e[v + k2] = ev;
                    zacc += ev;
                    s_key[rr + k2] = (g_mask[v + k2] != 0.f)
                        ? ((((unsigned long long)ordf(lv)) << 32)
                           | (unsigned long long)(~(unsigned)(v + k2)))
                        : 0ULL;
                }
            }
        }
        if (lane == 0) s_z[wid] = zacc;
        __syncthreads();
        if (wid == 0){
            float z = s_z[lane];
            #pragma unroll
            for (int off=16; off; off>>=1) z += __shfl_down_sync(0xffffffffu, z, off);
            if (lane == 0) atomicAdd(&g_Z[t & 1], z);
        }
        // per-warp bitonic sort; warp0 merges int8 top-28; 28 warps refine in fp32
        // (exact R6 reduction order); warp0 sorts refined keys -> g_cand top-20
        {
            unsigned long long kr = (tid < cnt) ? s_key[tid] : 0ULL;
            __syncthreads();                                      // s_key reads done
            kr = bitonic_desc(kr, lane);
            s_key[tid] = kr;                                      // lane i = i-th largest of warp
            __syncthreads();
            if (wid == 0){
                int ptr = 0;
                unsigned long long head = s_key[lane * 32];
                #pragma unroll
                for (int it = 0; it < KCAND; ++it){
                    unsigned long long m = wmax64(head);
                    unsigned ball = __ballot_sync(0xffffffffu, head == m);
                    int wl = __ffs(ball) - 1;
                    if (lane == wl){
                        ++ptr;
                        head = (ptr < 32) ? s_key[lane * 32 + ptr] : 0ULL;
                    }
                    if (lane == 0) s_m[it] = m;
                }
            }
            __syncthreads();
            if (wid < KCAND){
                unsigned long long key = s_m[wid];
                unsigned long long outk = 0ULL;
                if (key != 0ULL){
                    const int v = (int)(~(unsigned)(key & 0xffffffffu));
                    const float4* __restrict__ wr = ((const float4*)W_out) + (size_t)v * (Hdim/4);
                    float acc = 0.f;
                    #pragma unroll
                    for (int c = 0; c < 8; ++c){
                        const int idx = lane + (c << 5);
                        float4 w  = __ldcs(wr + idx);
                        float4 hh = s_h4[idx];
                        acc += w.x*hh.x + w.y*hh.y + w.z*hh.z + w.w*hh.w;
                    }
                    #pragma unroll
                    for (int off=16; off; off>>=1) acc += __shfl_down_sync(0xffffffffu, acc, off);
                    if (lane == 0){
                        float lv = acc + b_out[v];
                        outk = (((unsigned long long)ordf(lv)) << 32)
                             | (unsigned long long)(~(unsigned)v);
                    }
                }
                if (lane == 0) s_m[64 + wid] = outk;
            }
            __syncthreads();
            if (wid == 0){
                unsigned long long k = (lane < KCAND) ? s_m[64 + lane] : 0ULL;
                k = bitonic_desc(k, lane);                        // lane i = i-th largest
                if (lane < KTOP) g_cand[bid*KTOP + lane] = k;
            }
        }
        gridbar(&s_sense);

        // ============ Phase C: control (block0) overlapped with prob writes ============
        if (bid == 0){
            const int ncand = nb * KTOP;
            const int per = (ncand + 31) / 32;                    // <= 95
            const int base = wid * per;
            int mycnt = ncand - base;
            if (mycnt > per) mycnt = per; if (mycnt < 0) mycnt = 0;
            unsigned long long c0 = (lane      < mycnt) ? __ldcg(&g_cand[base + lane     ]) : 0ULL;
            unsigned long long c1 = (lane + 32 < mycnt) ? __ldcg(&g_cand[base + lane + 32]) : 0ULL;
            unsigned long long c2 = (lane + 64 < mycnt) ? __ldcg(&g_cand[base + lane + 64]) : 0ULL;
            #pragma unroll
            for (int it = 0; it < KTOP; ++it){                    // per-warp top-20 (shuffle-only)
                unsigned long long loc = c0;
                if (c1 > loc) loc = c1;
                if (c2 > loc) loc = c2;
                unsigned long long m = wmax64(loc);
                if      (c0 == m) c0 = 0ULL;
                else if (c1 == m) c1 = 0ULL;
                else if (c2 == m) c2 = 0ULL;
                if (lane == 0) s_m[wid*KTOP + it] = m;
            }
            __syncthreads();
            if (wid == 0){                                        // 32-way merge of sorted lists
                int ptr = 0;
                unsigned long long head = s_m[lane * KTOP];
                #pragma unroll
                for (int it = 0; it < KTOP; ++it){
                    unsigned long long m = wmax64(head);
                    unsigned ball = __ballot_sync(0xffffffffu, head == m);
                    int wl = __ffs(ball) - 1;
                    if (lane == wl){
                        ++ptr;
                        head = (ptr < KTOP) ? s_m[lane * KTOP + ptr] : 0ULL;
                    }
                    if (lane == 0) s_items[it] = (int)(~(unsigned)(m & 0xffffffffu));
                }
            }
            __syncthreads();
            // parallel hit check: one warp per candidate, lanes stride x[]
            if (wid < KTOP){
                const int want = s_items[wid] + 1;                // 1-indexed compare
                int h = 0;
                for (int jx = lane; jx < nx; jx += 32) h |= (x[jx] == want);
                h = __any_sync(0xffffffffu, h);
                if (lane == 0) s_hit[wid] = h;
            }
            __syncthreads();
            if (tid == 0){
                int card = 0, first = -1;
                #pragma unroll
                for (int k2 = 0; k2 < KTOP; ++k2){
                    if (s_hit[k2]){ ++card; if (first < 0) first = k2; }
                }
                const int ah = (card > 0) ? s_items[first] : s_items[0];
                const float fbn = (card > 0) ? 1.f : -1.f;
                s_ah = ah; s_fb = fbn;
                g_ahat = ah; g_fb = fbn;
                out[OFF_AHAT + t] = (float)ah;
                out[OFF_FB + t]   = fbn;
                __threadfence();
                atomicExch(&g_flag, t);                           // publish step-t control
            }
        }
        // all blocks: masked-prob writes (vectorized; overlaps block0's control)
        {
            const float Zinv = 1.0f / __ldcg(&g_Z[t & 1]);
            const int cnt4 = cnt >> 2;                            // v0 16B-aligned by chunk pad
            const float4* e4 = (const float4*)(g_e + v0);
            const float4* m4 = (const float4*)(g_mask + v0);
            float4* o4 = (float4*)(out + OFF_P + (size_t)t*Vdim + v0);
            for (int r = tid; r < cnt4; r += NTH){
                float4 e = e4[r];
                float4 m = m4[r];
                float4 p = make_float4(e.x*Zinv*m.x, e.y*Zinv*m.y, e.z*Zinv*m.z, e.w*Zinv*m.w);
                __stcs(o4 + r, p);
            }
        }
        if (bid != 0 && tid == 0){
            while (ldcg_s32(&g_flag) < t){ __nanosleep(32); }     // load-poll
            __threadfence();
            s_ah = __ldcg(&g_ahat);
            s_fb = __ldcg(&g_fb);
        }
        __syncthreads();                                          // s_ah/s_fb block-visible
    }
}

extern "C" void kernel_launch(void* const* d_in, const int* in_sizes, int n_in,
                              void* d_out, int out_size)
{
    const int*   x     = (const int*)  d_in[0];
    const float* embed = (const float*)d_in[1];
    const float* W_ih  = (const float*)d_in[2];
    const float* W_hh  = (const float*)d_in[3];
    const float* b_ih  = (const float*)d_in[4];
    const float* b_hh  = (const float*)d_in[5];
    const float* W_out = (const float*)d_in[6];
    const float* b_out = (const float*)d_in[7];
    float* out = (float*)d_out;
    const int nx = in_sizes[0];

    int dev = 0;
    cudaGetDevice(&dev);
    int sm = 148;
    cudaDeviceGetAttribute(&sm, cudaDevAttrMultiProcessorCount, dev);
    int grid = sm < MAXB ? sm : MAXB;   // 1024 thr/blk, 1 blk/SM -> all co-resident

    init_kernel<<<(Vdim + NTH - 1)/NTH, NTH>>>();
    quant_wout_kernel<<<grid, NTH>>>(W_out);
    lstm_rec_kernel<<<grid, NTH>>>(x, nx, embed, W_ih, W_hh, b_ih, b_hh, W_out, b_out, out);
}